// round 6
// baseline (speedup 1.0000x reference)
#include <cuda_runtime.h>

#define B_    32
#define C_    3
#define H_    512
#define W_    512
#define HW_   (H_ * W_)
#define R_    32                    // rows per warp task
#define NSTRIP 4                    // 128-col strips
#define NBAND (H_ / R_)             // 16
#define NTASK (B_ * NSTRIP * NBAND) // 2048 warp tasks
#define TPB   128                   // 4 warps/block
#define NBLK  (NTASK / (TPB / 32))  // 512 blocks

__device__ float g_partials[NBLK];
__device__ unsigned int g_count = 0;

struct RowD { float4 d; float dl, dr; };

// scalar gray-diff at element offset `off` within one image (b already applied)
__device__ __forceinline__ float gray1(const float* __restrict__ s,
                                       const float* __restrict__ h, size_t off)
{
    return 0.2989f * (s[off]           - h[off])
         + 0.587f  * (s[off +     HW_] - h[off +     HW_])
         + 0.114f  * (s[off + 2 * HW_] - h[off + 2 * HW_]);
}

__device__ __forceinline__ RowD load_row(const float* __restrict__ srb,
                                         const float* __restrict__ hrb,
                                         int row, int c4, int lane)
{
    RowD r;
    if (row < 0 || row >= H_) {           // warp-uniform branch
        r.d = make_float4(0.f, 0.f, 0.f, 0.f);
        r.dl = 0.f; r.dr = 0.f;
        return r;
    }
    size_t off = (size_t)row * W_ + c4;
    float4 s0 = *(const float4*)(srb + off);
    float4 s1 = *(const float4*)(srb + off + HW_);
    float4 s2 = *(const float4*)(srb + off + 2 * HW_);
    float4 h0 = *(const float4*)(hrb + off);
    float4 h1 = *(const float4*)(hrb + off + HW_);
    float4 h2 = *(const float4*)(hrb + off + 2 * HW_);
    r.d.x = 0.2989f * (s0.x - h0.x) + 0.587f * (s1.x - h1.x) + 0.114f * (s2.x - h2.x);
    r.d.y = 0.2989f * (s0.y - h0.y) + 0.587f * (s1.y - h1.y) + 0.114f * (s2.y - h2.y);
    r.d.z = 0.2989f * (s0.z - h0.z) + 0.587f * (s1.z - h1.z) + 0.114f * (s2.z - h2.z);
    r.d.w = 0.2989f * (s0.w - h0.w) + 0.587f * (s1.w - h1.w) + 0.114f * (s2.w - h2.w);

    r.dl = __shfl_up_sync(0xFFFFFFFFu, r.d.w, 1);
    r.dr = __shfl_down_sync(0xFFFFFFFFu, r.d.x, 1);
    if (lane == 0)
        r.dl = (c4 == 0)       ? 0.f : gray1(srb, hrb, off - 1);
    if (lane == 31)
        r.dr = (c4 + 4 == W_)  ? 0.f : gray1(srb, hrb, off + 4);
    return r;
}

__device__ __forceinline__ float sobel4(const RowD& t, const RowD& m, const RowD& b)
{
    float acc;
    // px0: left=dl, right=d.y
    {
        float gx = (t.dl - t.d.y) + 2.0f * (m.dl - m.d.y) + (b.dl - b.d.y);
        float gy = (t.dl + 2.0f * t.d.x + t.d.y) - (b.dl + 2.0f * b.d.x + b.d.y);
        acc = fabsf(gx) + fabsf(gy);
    }
    {
        float gx = (t.d.x - t.d.z) + 2.0f * (m.d.x - m.d.z) + (b.d.x - b.d.z);
        float gy = (t.d.x + 2.0f * t.d.y + t.d.z) - (b.d.x + 2.0f * b.d.y + b.d.z);
        acc += fabsf(gx) + fabsf(gy);
    }
    {
        float gx = (t.d.y - t.d.w) + 2.0f * (m.d.y - m.d.w) + (b.d.y - b.d.w);
        float gy = (t.d.y + 2.0f * t.d.z + t.d.w) - (b.d.y + 2.0f * b.d.z + b.d.w);
        acc += fabsf(gx) + fabsf(gy);
    }
    {
        float gx = (t.d.z - t.dr) + 2.0f * (m.d.z - m.dr) + (b.d.z - b.dr);
        float gy = (t.d.z + 2.0f * t.d.w + t.dr) - (b.d.z + 2.0f * b.d.w + b.dr);
        acc += fabsf(gx) + fabsf(gy);
    }
    return acc;
}

__global__ __launch_bounds__(TPB) void edge_loss_kernel(
    const float* __restrict__ sr, const float* __restrict__ hr,
    float* __restrict__ out)
{
    const int tid   = threadIdx.x;
    const int lane  = tid & 31;
    const int wtask = blockIdx.x * (TPB / 32) + (tid >> 5);

    const int b     = wtask / (NSTRIP * NBAND);
    const int rem   = wtask % (NSTRIP * NBAND);
    const int strip = rem / NBAND;
    const int band  = rem % NBAND;
    const int r0    = band * R_;
    const int c4    = strip * 128 + lane * 4;

    const float* srb = sr + (size_t)b * C_ * HW_;
    const float* hrb = hr + (size_t)b * C_ * HW_;

    RowD t = load_row(srb, hrb, r0 - 1, c4, lane);
    RowD m = load_row(srb, hrb, r0,     c4, lane);

    float acc = 0.0f;
    #pragma unroll 2
    for (int i = 0; i < R_; ++i) {
        RowD bt = load_row(srb, hrb, r0 + i + 1, c4, lane);
        acc += sobel4(t, m, bt);
        t = m; m = bt;
    }

    // Block reduce (4 warps)
    #pragma unroll
    for (int off = 16; off > 0; off >>= 1)
        acc += __shfl_xor_sync(0xFFFFFFFFu, acc, off);

    __shared__ float wsum[TPB / 32];
    __shared__ bool s_last;
    if (lane == 0) wsum[tid >> 5] = acc;
    __syncthreads();
    if (tid == 0) {
        float s = 0.0f;
        #pragma unroll
        for (int w = 0; w < TPB / 32; ++w) s += wsum[w];
        g_partials[blockIdx.x] = s;
        __threadfence();
        unsigned int prev = atomicAdd(&g_count, 1u);
        s_last = (prev == NBLK - 1);
    }
    __syncthreads();

    // Last block folds the final reduction (no second kernel launch)
    if (s_last) {
        __shared__ double sd[TPB];
        double a = 0.0;
        for (int i = tid; i < NBLK; i += TPB) a += (double)g_partials[i];
        sd[tid] = a;
        __syncthreads();
        #pragma unroll
        for (int off = TPB / 2; off > 0; off >>= 1) {
            if (tid < off) sd[tid] += sd[tid + off];
            __syncthreads();
        }
        if (tid == 0) {
            out[0] = (float)(sd[0] / (double)(B_ * (size_t)HW_));
            g_count = 0;   // reset for next replay (deterministic)
        }
    }
}

extern "C" void kernel_launch(void* const* d_in, const int* in_sizes, int n_in,
                              void* d_out, int out_size)
{
    const float* sr = (const float*)d_in[0];
    const float* hr = (const float*)d_in[1];
    float* out = (float*)d_out;

    edge_loss_kernel<<<NBLK, TPB>>>(sr, hr, out);
}

// round 7
// speedup vs baseline: 1.2998x; 1.2998x over previous
#include <cuda_runtime.h>

#define B_    32
#define C_    3
#define H_    512
#define W_    512
#define HW_   (H_ * W_)
#define ROWS  16
#define COLS  256                    // strip width
#define NSTRIP (W_ / COLS)           // 2
#define HB_   (H_ / ROWS)            // 32 bands
#define NBLK  (B_ * HB_ * NSTRIP)    // 2048 blocks
#define TPB   128
#define TROWS (ROWS + 2)             // 18
#define STR   260                    // smem row stride: [0]=left halo, [1..256], [257]=right

__device__ float g_partials[NBLK];
__device__ unsigned int g_count = 0;

__device__ __forceinline__ float gray1(const float* __restrict__ s,
                                       const float* __restrict__ h, size_t off)
{
    return 0.2989f * (s[off]           - h[off])
         + 0.587f  * (s[off +     HW_] - h[off +     HW_])
         + 0.114f  * (s[off + 2 * HW_] - h[off + 2 * HW_]);
}

__global__ __launch_bounds__(TPB, 12) void edge_loss_kernel(
    const float* __restrict__ sr, const float* __restrict__ hr,
    float* __restrict__ out)
{
    __shared__ float g[TROWS * STR];   // 18,720 B -> 12 CTAs/SM

    const int tid   = threadIdx.x;
    const int blk   = blockIdx.x;
    const int b     = blk / (HB_ * NSTRIP);
    const int rem   = blk % (HB_ * NSTRIP);
    const int band  = rem >> 1;
    const int strip = rem & 1;
    const int r0    = band * ROWS;
    const int c0    = strip * COLS;

    const float* srb = sr + (size_t)b * C_ * HW_;
    const float* hrb = hr + (size_t)b * C_ * HW_;

    // Edge columns: 18 rows x {left, right} = 36 tasks (scalar, L2-hit territory)
    if (tid < 2 * TROWS) {
        int tr   = tid >> 1;
        int side = tid & 1;
        int gr   = r0 + tr - 1;
        int gc   = side ? (c0 + COLS) : (c0 - 1);
        float v = 0.0f;
        if (gr >= 0 && gr < H_ && gc >= 0 && gc < W_)
            v = gray1(srb, hrb, (size_t)gr * W_ + gc);
        g[tr * STR + (side ? (COLS + 1) : 0)] = v;
    }

    // Main tile: 18 rows x 64 float4-chunks = 1152 tasks, 9 per thread
    #pragma unroll
    for (int it = 0; it < (TROWS * (COLS / 4)) / TPB; ++it) {
        int idx   = tid + it * TPB;
        int tr    = idx >> 6;          // / 64
        int chunk = idx & 63;
        int gr    = r0 + tr - 1;

        float4 d = make_float4(0.f, 0.f, 0.f, 0.f);
        if (gr >= 0 && gr < H_) {
            size_t off = (size_t)gr * W_ + c0 + chunk * 4;
            float4 s0 = *(const float4*)(srb + 0 * HW_ + off);
            float4 s1 = *(const float4*)(srb + 1 * HW_ + off);
            float4 s2 = *(const float4*)(srb + 2 * HW_ + off);
            float4 h0 = *(const float4*)(hrb + 0 * HW_ + off);
            float4 h1 = *(const float4*)(hrb + 1 * HW_ + off);
            float4 h2 = *(const float4*)(hrb + 2 * HW_ + off);
            d.x = 0.2989f * (s0.x - h0.x) + 0.587f * (s1.x - h1.x) + 0.114f * (s2.x - h2.x);
            d.y = 0.2989f * (s0.y - h0.y) + 0.587f * (s1.y - h1.y) + 0.114f * (s2.y - h2.y);
            d.z = 0.2989f * (s0.z - h0.z) + 0.587f * (s1.z - h1.z) + 0.114f * (s2.z - h2.z);
            d.w = 0.2989f * (s0.w - h0.w) + 0.587f * (s1.w - h1.w) + 0.114f * (s2.w - h2.w);
        }
        float* dst = g + tr * STR + 1 + chunk * 4;
        dst[0] = d.x; dst[1] = d.y; dst[2] = d.z; dst[3] = d.w;
    }
    __syncthreads();

    // Sobel + abs + accumulate: 16 x 256 = 4096 px, 32 per thread (scalar LDS, proven)
    float acc = 0.0f;
    #pragma unroll 4
    for (int it = 0; it < (ROWS * COLS) / TPB; ++it) {
        int idx = tid + it * TPB;
        int rr  = idx >> 8;            // / 256 -> 0..15
        int c   = idx & 255;
        const float* p = g + rr * STR + c;   // top-left of 3x3 neighborhood
        float a00 = p[0],           a01 = p[1],           a02 = p[2];
        float a10 = p[STR],                               a12 = p[STR + 2];
        float a20 = p[2 * STR],     a21 = p[2 * STR + 1], a22 = p[2 * STR + 2];
        float gx = (a00 - a02) + 2.0f * (a10 - a12) + (a20 - a22);
        float gy = (a00 - a20) + 2.0f * (a01 - a21) + (a02 - a22);
        acc += fabsf(gx) + fabsf(gy);
    }

    // Block reduce (4 warps)
    #pragma unroll
    for (int off = 16; off > 0; off >>= 1)
        acc += __shfl_xor_sync(0xFFFFFFFFu, acc, off);

    __shared__ float wsum[TPB / 32];
    __shared__ bool s_last;
    if ((tid & 31) == 0) wsum[tid >> 5] = acc;
    __syncthreads();
    if (tid == 0) {
        float s = 0.0f;
        #pragma unroll
        for (int w = 0; w < TPB / 32; ++w) s += wsum[w];
        g_partials[blockIdx.x] = s;
        __threadfence();
        unsigned int prev = atomicAdd(&g_count, 1u);
        s_last = (prev == NBLK - 1);
    }
    __syncthreads();

    // Last block folds the final reduction (no second kernel launch)
    if (s_last) {
        double* sd = (double*)g;   // reuse tile smem
        double a = 0.0;
        for (int i = tid; i < NBLK; i += TPB) a += (double)g_partials[i];
        sd[tid] = a;
        __syncthreads();
        #pragma unroll
        for (int off = TPB / 2; off > 0; off >>= 1) {
            if (tid < off) sd[tid] += sd[tid + off];
            __syncthreads();
        }
        if (tid == 0) {
            out[0] = (float)(sd[0] / (double)(B_ * (size_t)HW_));
            g_count = 0;   // reset for next replay (deterministic)
        }
    }
}

extern "C" void kernel_launch(void* const* d_in, const int* in_sizes, int n_in,
                              void* d_out, int out_size)
{
    const float* sr = (const float*)d_in[0];
    const float* hr = (const float*)d_in[1];
    float* out = (float*)d_out;

    edge_loss_kernel<<<NBLK, TPB>>>(sr, hr, out);
}

// round 8
// speedup vs baseline: 1.5279x; 1.1755x over previous
#include <cuda_runtime.h>
#include <cuda_fp16.h>

#define B_   32
#define C_   3
#define H_   512
#define W_   512
#define HW_  (H_ * W_)
#define ROWS 16
#define HB_  (H_ / ROWS)          // 32 row-bands per image
#define NBLK (B_ * HB_)           // 1024 blocks (single resident wave at 8 CTAs/SM)
#define TPB  256
#define TROWS (ROWS + 2)          // 18 tile rows (with halo)
#define STR  516                  // smem row stride in halves (1032 B, 4B-aligned)

// Tile layout (halves): image col c -> tile index c+2 (even => 4B-aligned half2 stores)
// left halo at index 1, right halo at index 514.

__device__ float g_partials[NBLK];

__global__ __launch_bounds__(TPB, 8) void edge_partial_kernel(
    const float* __restrict__ sr, const float* __restrict__ hr)
{
    __shared__ __half g[TROWS * STR];   // 18,576 B -> 8 CTAs/SM

    const int tid = threadIdx.x;
    const int b  = blockIdx.x / HB_;
    const int r0 = (blockIdx.x % HB_) * ROWS;

    const float* srb = sr + (size_t)b * C_ * HW_;
    const float* hrb = hr + (size_t)b * C_ * HW_;

    // Zero halo columns: indices 0,1 (left) and 514,515 (right) per row
    if (tid < 4 * TROWS) {
        int tr = tid >> 2;
        int k  = tid & 3;
        int col = (k < 2) ? k : (512 + k);   // 0,1,514,515
        g[tr * STR + col] = __float2half(0.0f);
    }

    // Load halo'd gray-diff tile: 18 rows x 128 float4-chunks = 2304 tasks, 9/thread
    // unroll 1: keeps 6 float4 in flight within the 32-reg budget, no spills
    #pragma unroll 1
    for (int it = 0; it < (TROWS * (W_ / 4)) / TPB; ++it) {
        int idx   = tid + it * TPB;
        int tr    = idx >> 7;          // / 128
        int chunk = idx & 127;
        int gr    = r0 + tr - 1;

        float4 d = make_float4(0.f, 0.f, 0.f, 0.f);
        if (gr >= 0 && gr < H_) {
            size_t off = (size_t)gr * W_ + chunk * 4;
            float4 s0 = *(const float4*)(srb + 0 * HW_ + off);
            float4 s1 = *(const float4*)(srb + 1 * HW_ + off);
            float4 s2 = *(const float4*)(srb + 2 * HW_ + off);
            float4 h0 = *(const float4*)(hrb + 0 * HW_ + off);
            float4 h1 = *(const float4*)(hrb + 1 * HW_ + off);
            float4 h2 = *(const float4*)(hrb + 2 * HW_ + off);
            d.x = 0.2989f * (s0.x - h0.x) + 0.587f * (s1.x - h1.x) + 0.114f * (s2.x - h2.x);
            d.y = 0.2989f * (s0.y - h0.y) + 0.587f * (s1.y - h1.y) + 0.114f * (s2.y - h2.y);
            d.z = 0.2989f * (s0.z - h0.z) + 0.587f * (s1.z - h1.z) + 0.114f * (s2.z - h2.z);
            d.w = 0.2989f * (s0.w - h0.w) + 0.587f * (s1.w - h1.w) + 0.114f * (s2.w - h2.w);
        }
        // image col chunk*4 -> tile index chunk*4 + 2 (4B-aligned half2 stores)
        __half2* dst = (__half2*)&g[tr * STR + 2 + chunk * 4];
        dst[0] = __floats2half2_rn(d.x, d.y);
        dst[1] = __floats2half2_rn(d.z, d.w);
    }
    __syncthreads();

    // Sobel + abs + accumulate: 16 rows x 512 cols = 8192 px, 32/thread
    // pixel c: left neighbor at tile index c+1 => p = row*STR + c + 1
    float acc = 0.0f;
    #pragma unroll 4
    for (int it = 0; it < (ROWS * W_) / TPB; ++it) {
        int idx = tid + it * TPB;
        int rr  = idx >> 9;            // / 512  -> 0..15
        int c   = idx & 511;
        const __half* p = g + rr * STR + c + 1;   // top-left of 3x3 neighborhood
        float a00 = __half2float(p[0]);
        float a01 = __half2float(p[1]);
        float a02 = __half2float(p[2]);
        float a10 = __half2float(p[STR]);
        float a12 = __half2float(p[STR + 2]);
        float a20 = __half2float(p[2 * STR]);
        float a21 = __half2float(p[2 * STR + 1]);
        float a22 = __half2float(p[2 * STR + 2]);
        float gx = (a00 - a02) + 2.0f * (a10 - a12) + (a20 - a22);
        float gy = (a00 - a20) + 2.0f * (a01 - a21) + (a02 - a22);
        acc += fabsf(gx) + fabsf(gy);
    }

    // Block reduce to one partial
    #pragma unroll
    for (int off = 16; off > 0; off >>= 1)
        acc += __shfl_xor_sync(0xFFFFFFFFu, acc, off);

    __shared__ float wsum[TPB / 32];
    if ((tid & 31) == 0) wsum[tid >> 5] = acc;
    __syncthreads();
    if (tid == 0) {
        float s = 0.0f;
        #pragma unroll
        for (int w = 0; w < TPB / 32; ++w) s += wsum[w];
        g_partials[blockIdx.x] = s;
    }
}

__global__ __launch_bounds__(TPB) void edge_finalize_kernel(float* __restrict__ out)
{
    __shared__ double s[TPB];
    double a = 0.0;
    for (int i = threadIdx.x; i < NBLK; i += TPB) a += (double)g_partials[i];
    s[threadIdx.x] = a;
    __syncthreads();
    #pragma unroll
    for (int off = TPB / 2; off > 0; off >>= 1) {
        if (threadIdx.x < off) s[threadIdx.x] += s[threadIdx.x + off];
        __syncthreads();
    }
    if (threadIdx.x == 0)
        out[0] = (float)(s[0] / (double)(B_ * (size_t)HW_));
}

extern "C" void kernel_launch(void* const* d_in, const int* in_sizes, int n_in,
                              void* d_out, int out_size)
{
    const float* sr = (const float*)d_in[0];
    const float* hr = (const float*)d_in[1];
    float* out = (float*)d_out;

    edge_partial_kernel<<<NBLK, TPB>>>(sr, hr);
    edge_finalize_kernel<<<1, TPB>>>(out);
}

// round 9
// speedup vs baseline: 1.6674x; 1.0913x over previous
#include <cuda_runtime.h>
#include <cuda_fp16.h>

#define B_   32
#define C_   3
#define H_   512
#define W_   512
#define HW_  (H_ * W_)
#define ROWS 16
#define HB_  (H_ / ROWS)          // 32 row-bands per image
#define NBLK (B_ * HB_)           // 1024 blocks
#define TPB  256
#define TROWS (ROWS + 2)          // 18 tile rows (with halo)
#define STR  516                  // smem row stride in halves (1032 B)

// Tile layout (halves): image col c -> index c+2 (even -> 4B-aligned half2 ops)
// left halo (col -1) at index 1, right halo (col 512) at index 514.
// indices 0 and 515 zeroed (read by the even-aligned neighbor loads).

__device__ float g_partials[NBLK];

__global__ __launch_bounds__(TPB, 7) void edge_partial_kernel(
    const float* __restrict__ sr, const float* __restrict__ hr)
{
    __shared__ __half g[TROWS * STR];   // 18,576 B -> 7 CTAs/SM (single wave)

    const int tid = threadIdx.x;
    const int b  = blockIdx.x / HB_;
    const int r0 = (blockIdx.x % HB_) * ROWS;

    const float* srb = sr + (size_t)b * C_ * HW_;
    const float* hrb = hr + (size_t)b * C_ * HW_;

    // Zero halo columns: indices 0,1 (left) and 514,515 (right) per tile row
    if (tid < 2 * TROWS) {
        int tr   = tid >> 1;
        int side = tid & 1;
        __half2* dst = (__half2*)&g[tr * STR + (side ? 514 : 0)];
        *dst = __floats2half2_rn(0.0f, 0.0f);
    }

    // Load halo'd gray-diff tile: 18 rows x 128 float4-chunks = 2304 tasks, 9/thread
    // FULL unroll: front-batch LDGs for MLP (the thing R7 broke)
    #pragma unroll
    for (int it = 0; it < (TROWS * (W_ / 4)) / TPB; ++it) {
        int idx   = tid + it * TPB;
        int tr    = idx >> 7;          // / 128
        int chunk = idx & 127;
        int gr    = r0 + tr - 1;

        float4 d = make_float4(0.f, 0.f, 0.f, 0.f);
        if (gr >= 0 && gr < H_) {
            size_t off = (size_t)gr * W_ + chunk * 4;
            float4 s0 = *(const float4*)(srb + 0 * HW_ + off);
            float4 s1 = *(const float4*)(srb + 1 * HW_ + off);
            float4 s2 = *(const float4*)(srb + 2 * HW_ + off);
            float4 h0 = *(const float4*)(hrb + 0 * HW_ + off);
            float4 h1 = *(const float4*)(hrb + 1 * HW_ + off);
            float4 h2 = *(const float4*)(hrb + 2 * HW_ + off);
            d.x = 0.2989f * (s0.x - h0.x) + 0.587f * (s1.x - h1.x) + 0.114f * (s2.x - h2.x);
            d.y = 0.2989f * (s0.y - h0.y) + 0.587f * (s1.y - h1.y) + 0.114f * (s2.y - h2.y);
            d.z = 0.2989f * (s0.z - h0.z) + 0.587f * (s1.z - h1.z) + 0.114f * (s2.z - h2.z);
            d.w = 0.2989f * (s0.w - h0.w) + 0.587f * (s1.w - h1.w) + 0.114f * (s2.w - h2.w);
        }
        __half2* dst = (__half2*)&g[tr * STR + 2 + chunk * 4];   // 4B-aligned
        dst[0] = __floats2half2_rn(d.x, d.y);
        dst[1] = __floats2half2_rn(d.z, d.w);
    }
    __syncthreads();

    // Compute phase: 2 pixels per step (pair c, c+1), half2 SIMD.
    // Needs cols c-1..c+2 = indices c+1..c+4. Even-aligned half2 loads:
    //   P=(idx c,c+1), Q=(idx c+2,c+3), R=(idx c+4,c+5)
    //   A=(col c-1,c)=(P.y,Q.x)  B=(col c,c+1)=Q  C=(col c+1,c+2)=(Q.y,R.x)
    // gx2 = (A0-C0) + 2(A1-C1) + (A2-C2)
    // gy2 = (A0+2B0+C0) - (A2+2B2+C2)
    const __half2 two = __floats2half2_rn(2.0f, 2.0f);
    float acc = 0.0f;
    #pragma unroll 4
    for (int it = 0; it < (ROWS * (W_ / 2)) / TPB; ++it) {   // 16 iters
        int idx = tid + it * TPB;
        int rr  = idx >> 8;            // / 256 -> 0..15
        int c   = (idx & 255) * 2;     // even col of the pair
        const __half2* p0 = (const __half2*)&g[rr * STR + c];
        const __half2* p1 = (const __half2*)&g[(rr + 1) * STR + c];
        const __half2* p2 = (const __half2*)&g[(rr + 2) * STR + c];

        __half2 P0 = p0[0], Q0 = p0[1], R0 = p0[2];
        __half2 P1 = p1[0], Q1 = p1[1], R1 = p1[2];
        __half2 P2 = p2[0], Q2 = p2[1], R2 = p2[2];

        __half2 A0 = __halves2half2(__high2half(P0), __low2half(Q0));
        __half2 C0 = __halves2half2(__high2half(Q0), __low2half(R0));
        __half2 A1 = __halves2half2(__high2half(P1), __low2half(Q1));
        __half2 C1 = __halves2half2(__high2half(Q1), __low2half(R1));
        __half2 A2 = __halves2half2(__high2half(P2), __low2half(Q2));
        __half2 C2 = __halves2half2(__high2half(Q2), __low2half(R2));

        __half2 gx2 = __hfma2(two, __hsub2(A1, C1),
                              __hadd2(__hsub2(A0, C0), __hsub2(A2, C2)));
        __half2 t0  = __hfma2(two, Q0, __hadd2(A0, C0));
        __half2 t2  = __hfma2(two, Q2, __hadd2(A2, C2));
        __half2 gy2 = __hsub2(t0, t2);

        float2 fx = __half22float2(gx2);
        float2 fy = __half22float2(gy2);
        acc += fabsf(fx.x) + fabsf(fx.y) + fabsf(fy.x) + fabsf(fy.y);
    }

    // Block reduce to one partial
    #pragma unroll
    for (int off = 16; off > 0; off >>= 1)
        acc += __shfl_xor_sync(0xFFFFFFFFu, acc, off);

    __shared__ float wsum[TPB / 32];
    if ((tid & 31) == 0) wsum[tid >> 5] = acc;
    __syncthreads();
    if (tid == 0) {
        float s = 0.0f;
        #pragma unroll
        for (int w = 0; w < TPB / 32; ++w) s += wsum[w];
        g_partials[blockIdx.x] = s;
    }
}

__global__ __launch_bounds__(TPB) void edge_finalize_kernel(float* __restrict__ out)
{
    __shared__ double s[TPB];
    double a = 0.0;
    for (int i = threadIdx.x; i < NBLK; i += TPB) a += (double)g_partials[i];
    s[threadIdx.x] = a;
    __syncthreads();
    #pragma unroll
    for (int off = TPB / 2; off > 0; off >>= 1) {
        if (threadIdx.x < off) s[threadIdx.x] += s[threadIdx.x + off];
        __syncthreads();
    }
    if (threadIdx.x == 0)
        out[0] = (float)(s[0] / (double)(B_ * (size_t)HW_));
}

extern "C" void kernel_launch(void* const* d_in, const int* in_sizes, int n_in,
                              void* d_out, int out_size)
{
    const float* sr = (const float*)d_in[0];
    const float* hr = (const float*)d_in[1];
    float* out = (float*)d_out;

    edge_partial_kernel<<<NBLK, TPB>>>(sr, hr);
    edge_finalize_kernel<<<1, TPB>>>(out);
}

// round 10
// speedup vs baseline: 1.7224x; 1.0330x over previous
#include <cuda_runtime.h>
#include <cuda_fp16.h>

#define B_   32
#define C_   3
#define H_   512
#define W_   512
#define HW_  (H_ * W_)
#define ROWS 16
#define HB_  (H_ / ROWS)          // 32 row-bands per image
#define NBLK (B_ * HB_)           // 1024 blocks
#define TPB  256
#define TROWS (ROWS + 2)          // 18 tile rows (with halo)
#define STR  516                  // smem row stride in halves (1032 B)

// Tile layout (halves): image col c -> index c+2 (even -> 4B-aligned half2 ops)
// left halo (col -1) at index 1, right halo (col 512) at index 514.
// indices 0 and 515 zeroed.

__device__ float g_accum = 0.0f;
__device__ unsigned int g_count = 0;

__global__ __launch_bounds__(TPB, 7) void edge_loss_kernel(
    const float* __restrict__ sr, const float* __restrict__ hr,
    float* __restrict__ out)
{
    __shared__ __half g[TROWS * STR];   // 18,576 B -> 7 CTAs/SM (single wave)

    const int tid = threadIdx.x;
    const int b  = blockIdx.x / HB_;
    const int r0 = (blockIdx.x % HB_) * ROWS;

    const float* srb = sr + (size_t)b * C_ * HW_;
    const float* hrb = hr + (size_t)b * C_ * HW_;

    // Zero halo columns: indices 0,1 (left) and 514,515 (right) per tile row
    if (tid < 2 * TROWS) {
        int tr   = tid >> 1;
        int side = tid & 1;
        __half2* dst = (__half2*)&g[tr * STR + (side ? 514 : 0)];
        *dst = __floats2half2_rn(0.0f, 0.0f);
    }

    // Load halo'd gray-diff tile: 18 rows x 128 float4-chunks = 2304 tasks, 9/thread
    // FULL unroll: front-batched LDGs for MLP (proven in R1/R8)
    #pragma unroll
    for (int it = 0; it < (TROWS * (W_ / 4)) / TPB; ++it) {
        int idx   = tid + it * TPB;
        int tr    = idx >> 7;          // / 128
        int chunk = idx & 127;
        int gr    = r0 + tr - 1;

        float4 d = make_float4(0.f, 0.f, 0.f, 0.f);
        if (gr >= 0 && gr < H_) {
            size_t off = (size_t)gr * W_ + chunk * 4;
            float4 s0 = *(const float4*)(srb + 0 * HW_ + off);
            float4 s1 = *(const float4*)(srb + 1 * HW_ + off);
            float4 s2 = *(const float4*)(srb + 2 * HW_ + off);
            float4 h0 = *(const float4*)(hrb + 0 * HW_ + off);
            float4 h1 = *(const float4*)(hrb + 1 * HW_ + off);
            float4 h2 = *(const float4*)(hrb + 2 * HW_ + off);
            d.x = 0.2989f * (s0.x - h0.x) + 0.587f * (s1.x - h1.x) + 0.114f * (s2.x - h2.x);
            d.y = 0.2989f * (s0.y - h0.y) + 0.587f * (s1.y - h1.y) + 0.114f * (s2.y - h2.y);
            d.z = 0.2989f * (s0.z - h0.z) + 0.587f * (s1.z - h1.z) + 0.114f * (s2.z - h2.z);
            d.w = 0.2989f * (s0.w - h0.w) + 0.587f * (s1.w - h1.w) + 0.114f * (s2.w - h2.w);
        }
        __half2* dst = (__half2*)&g[tr * STR + 2 + chunk * 4];   // 4B-aligned
        dst[0] = __floats2half2_rn(d.x, d.y);
        dst[1] = __floats2half2_rn(d.z, d.w);
    }
    __syncthreads();

    // Compute phase: 4 pixels per iter, half2 SIMD. 8 iters.
    // Pixels p=c4..c4+3 need cols c4-1..c4+4 = tile indices c4+1..c4+6.
    // Load even-aligned indices c4..c4+7 as 4 half2: P,Q,R,S per row.
    //   pair0 (p=c4,c4+1):   A=(P.hi,Q.lo) B=Q C=(Q.hi,R.lo)
    //   pair1 (p=c4+2,c4+3): A=(Q.hi,R.lo) B=R C=(R.hi,S.lo)
    const __half2 two = __floats2half2_rn(2.0f, 2.0f);
    float acc = 0.0f;
    #pragma unroll
    for (int it = 0; it < (ROWS * (W_ / 4)) / TPB; ++it) {   // 8 iters
        int idx = tid + it * TPB;
        int rr  = idx >> 7;            // 0..15
        int c4  = (idx & 127) * 4;     // 0,4,...,508
        const __half2* p0 = (const __half2*)&g[rr * STR + c4];
        const __half2* p1 = (const __half2*)&g[(rr + 1) * STR + c4];
        const __half2* p2 = (const __half2*)&g[(rr + 2) * STR + c4];

        __half2 P0 = p0[0], Q0 = p0[1], R0 = p0[2], S0 = p0[3];
        __half2 P1 = p1[0], Q1 = p1[1], R1 = p1[2], S1 = p1[3];
        __half2 P2 = p2[0], Q2 = p2[1], R2 = p2[2], S2 = p2[3];

        // row-wise neighbor pairs
        __half2 A0r0 = __halves2half2(__high2half(P0), __low2half(Q0));
        __half2 C0r0 = __halves2half2(__high2half(Q0), __low2half(R0));
        __half2 C1r0 = __halves2half2(__high2half(R0), __low2half(S0));
        __half2 A0r1 = __halves2half2(__high2half(P1), __low2half(Q1));
        __half2 C0r1 = __halves2half2(__high2half(Q1), __low2half(R1));
        __half2 C1r1 = __halves2half2(__high2half(R1), __low2half(S1));
        __half2 A0r2 = __halves2half2(__high2half(P2), __low2half(Q2));
        __half2 C0r2 = __halves2half2(__high2half(Q2), __low2half(R2));
        __half2 C1r2 = __halves2half2(__high2half(R2), __low2half(S2));

        // pair0
        {
            __half2 gx2 = __hfma2(two, __hsub2(A0r1, C0r1),
                                  __hadd2(__hsub2(A0r0, C0r0), __hsub2(A0r2, C0r2)));
            __half2 t0  = __hfma2(two, Q0, __hadd2(A0r0, C0r0));
            __half2 t2  = __hfma2(two, Q2, __hadd2(A0r2, C0r2));
            __half2 gy2 = __hsub2(t0, t2);
            float2 fx = __half22float2(gx2);
            float2 fy = __half22float2(gy2);
            acc += fabsf(fx.x) + fabsf(fx.y) + fabsf(fy.x) + fabsf(fy.y);
        }
        // pair1 (A = pair0's C)
        {
            __half2 gx2 = __hfma2(two, __hsub2(C0r1, C1r1),
                                  __hadd2(__hsub2(C0r0, C1r0), __hsub2(C0r2, C1r2)));
            __half2 t0  = __hfma2(two, R0, __hadd2(C0r0, C1r0));
            __half2 t2  = __hfma2(two, R2, __hadd2(C0r2, C1r2));
            __half2 gy2 = __hsub2(t0, t2);
            float2 fx = __half22float2(gx2);
            float2 fy = __half22float2(gy2);
            acc += fabsf(fx.x) + fabsf(fx.y) + fabsf(fy.x) + fabsf(fy.y);
        }
    }

    // Block reduce
    #pragma unroll
    for (int off = 16; off > 0; off >>= 1)
        acc += __shfl_xor_sync(0xFFFFFFFFu, acc, off);

    __shared__ float wsum[TPB / 32];
    if ((tid & 31) == 0) wsum[tid >> 5] = acc;
    __syncthreads();

    // tid0: one fire-and-forget atomic per block; NO trailing barrier.
    if (tid == 0) {
        float s = 0.0f;
        #pragma unroll
        for (int w = 0; w < TPB / 32; ++w) s += wsum[w];
        atomicAdd(&g_accum, s);
        __threadfence();
        unsigned int prev = atomicAdd(&g_count, 1u);
        if (prev == NBLK - 1) {
            float tot = atomicAdd(&g_accum, 0.0f);   // coherent L2 read
            out[0] = tot / (float)(B_ * (size_t)HW_);
            g_accum = 0.0f;   // reset for next replay
            g_count = 0;
        }
    }
}

extern "C" void kernel_launch(void* const* d_in, const int* in_sizes, int n_in,
                              void* d_out, int out_size)
{
    const float* sr = (const float*)d_in[0];
    const float* hr = (const float*)d_in[1];
    float* out = (float*)d_out;

    edge_loss_kernel<<<NBLK, TPB>>>(sr, hr, out);
}

// round 11
// speedup vs baseline: 1.7330x; 1.0062x over previous
#include <cuda_runtime.h>
#include <cuda_fp16.h>

#define B_   32
#define C_   3
#define H_   512
#define W_   512
#define HW_  (H_ * W_)
#define ROWS 16
#define HB_  (H_ / ROWS)          // 32 row-bands per image
#define NBLK (B_ * HB_)           // 1024 blocks
#define TPB  256
#define TROWS (ROWS + 2)          // 18 tile rows (with halo)
#define STR  516                  // smem row stride in halves (1032 B)

// Tile layout (halves): image col c -> index c+2 (even -> 4B-aligned half2 ops)
// left halo (col -1) at index 1, right halo (col 512) at index 514.
// indices 0 and 515 zeroed.

__device__ float g_accum = 0.0f;
__device__ unsigned int g_count = 0;

__global__ __launch_bounds__(TPB, 8) void edge_loss_kernel(
    const float* __restrict__ sr, const float* __restrict__ hr,
    float* __restrict__ out)
{
    __shared__ __half g[TROWS * STR];   // 18,576 B -> 8 CTAs/SM (single wave)

    const int tid = threadIdx.x;
    const int b  = blockIdx.x / HB_;
    const int r0 = (blockIdx.x % HB_) * ROWS;

    const float* srb = sr + (size_t)b * C_ * HW_;
    const float* hrb = hr + (size_t)b * C_ * HW_;

    // Zero halo columns: indices 0,1 (left) and 514,515 (right) per tile row
    if (tid < 2 * TROWS) {
        int tr   = tid >> 1;
        int side = tid & 1;
        __half2* dst = (__half2*)&g[tr * STR + (side ? 514 : 0)];
        *dst = __floats2half2_rn(0.0f, 0.0f);
    }

    // Load halo'd gray-diff tile: 18 rows x 128 float4-chunks = 2304 tasks, 9/thread
    // FULL unroll: front-batched LDGs for MLP (proven)
    #pragma unroll
    for (int it = 0; it < (TROWS * (W_ / 4)) / TPB; ++it) {
        int idx   = tid + it * TPB;
        int tr    = idx >> 7;          // / 128
        int chunk = idx & 127;
        int gr    = r0 + tr - 1;

        float4 d = make_float4(0.f, 0.f, 0.f, 0.f);
        if (gr >= 0 && gr < H_) {
            size_t off = (size_t)gr * W_ + chunk * 4;
            float4 s0 = *(const float4*)(srb + 0 * HW_ + off);
            float4 s1 = *(const float4*)(srb + 1 * HW_ + off);
            float4 s2 = *(const float4*)(srb + 2 * HW_ + off);
            float4 h0 = *(const float4*)(hrb + 0 * HW_ + off);
            float4 h1 = *(const float4*)(hrb + 1 * HW_ + off);
            float4 h2 = *(const float4*)(hrb + 2 * HW_ + off);
            d.x = 0.2989f * (s0.x - h0.x) + 0.587f * (s1.x - h1.x) + 0.114f * (s2.x - h2.x);
            d.y = 0.2989f * (s0.y - h0.y) + 0.587f * (s1.y - h1.y) + 0.114f * (s2.y - h2.y);
            d.z = 0.2989f * (s0.z - h0.z) + 0.587f * (s1.z - h1.z) + 0.114f * (s2.z - h2.z);
            d.w = 0.2989f * (s0.w - h0.w) + 0.587f * (s1.w - h1.w) + 0.114f * (s2.w - h2.w);
        }
        __half2* dst = (__half2*)&g[tr * STR + 2 + chunk * 4];   // 4B-aligned
        dst[0] = __floats2half2_rn(d.x, d.y);
        dst[1] = __floats2half2_rn(d.z, d.w);
    }
    __syncthreads();

    // Compute phase: 4 pixels per iter, half2 SIMD. 8 iters.
    // Pixels p=c4..c4+3 need cols c4-1..c4+4 = tile indices c4+1..c4+6.
    // Load even-aligned indices c4..c4+7 as 4 half2: P,Q,R,S per row.
    const __half2 two = __floats2half2_rn(2.0f, 2.0f);
    float acc = 0.0f;
    #pragma unroll
    for (int it = 0; it < (ROWS * (W_ / 4)) / TPB; ++it) {   // 8 iters
        int idx = tid + it * TPB;
        int rr  = idx >> 7;            // 0..15
        int c4  = (idx & 127) * 4;     // 0,4,...,508
        const __half2* p0 = (const __half2*)&g[rr * STR + c4];
        const __half2* p1 = (const __half2*)&g[(rr + 1) * STR + c4];
        const __half2* p2 = (const __half2*)&g[(rr + 2) * STR + c4];

        __half2 P0 = p0[0], Q0 = p0[1], R0 = p0[2], S0 = p0[3];
        __half2 P1 = p1[0], Q1 = p1[1], R1 = p1[2], S1 = p1[3];
        __half2 P2 = p2[0], Q2 = p2[1], R2 = p2[2], S2 = p2[3];

        // row-wise shifted neighbor pairs
        __half2 A0r0 = __halves2half2(__high2half(P0), __low2half(Q0));
        __half2 C0r0 = __halves2half2(__high2half(Q0), __low2half(R0));
        __half2 C1r0 = __halves2half2(__high2half(R0), __low2half(S0));
        __half2 A0r1 = __halves2half2(__high2half(P1), __low2half(Q1));
        __half2 C0r1 = __halves2half2(__high2half(Q1), __low2half(R1));
        __half2 C1r1 = __halves2half2(__high2half(R1), __low2half(S1));
        __half2 A0r2 = __halves2half2(__high2half(P2), __low2half(Q2));
        __half2 C0r2 = __halves2half2(__high2half(Q2), __low2half(R2));
        __half2 C1r2 = __halves2half2(__high2half(R2), __low2half(S2));

        // pair0 (pixels c4, c4+1)
        __half2 gx0 = __hfma2(two, __hsub2(A0r1, C0r1),
                              __hadd2(__hsub2(A0r0, C0r0), __hsub2(A0r2, C0r2)));
        __half2 gy0 = __hsub2(__hfma2(two, Q0, __hadd2(A0r0, C0r0)),
                              __hfma2(two, Q2, __hadd2(A0r2, C0r2)));
        // pair1 (pixels c4+2, c4+3)
        __half2 gx1 = __hfma2(two, __hsub2(C0r1, C1r1),
                              __hadd2(__hsub2(C0r0, C1r0), __hsub2(C0r2, C1r2)));
        __half2 gy1 = __hsub2(__hfma2(two, R0, __hadd2(C0r0, C1r0)),
                              __hfma2(two, R2, __hadd2(C0r2, C1r2)));

        // |gx|+|gy| for all 4 pixels, accumulated in half2, one convert per iter
        __half2 s2h = __hadd2(__hadd2(__habs2(gx0), __habs2(gy0)),
                              __hadd2(__habs2(gx1), __habs2(gy1)));
        float2 sf = __half22float2(s2h);
        acc += sf.x + sf.y;
    }

    // Block reduce
    #pragma unroll
    for (int off = 16; off > 0; off >>= 1)
        acc += __shfl_xor_sync(0xFFFFFFFFu, acc, off);

    __shared__ float wsum[TPB / 32];
    if ((tid & 31) == 0) wsum[tid >> 5] = acc;
    __syncthreads();

    // tid0: one fire-and-forget atomic per block; NO trailing barrier.
    if (tid == 0) {
        float s = 0.0f;
        #pragma unroll
        for (int w = 0; w < TPB / 32; ++w) s += wsum[w];
        atomicAdd(&g_accum, s);
        __threadfence();
        unsigned int prev = atomicAdd(&g_count, 1u);
        if (prev == NBLK - 1) {
            float tot = atomicAdd(&g_accum, 0.0f);   // coherent L2 read
            out[0] = tot / (float)(B_ * (size_t)HW_);
            g_accum = 0.0f;   // reset for next replay
            g_count = 0;
        }
    }
}

extern "C" void kernel_launch(void* const* d_in, const int* in_sizes, int n_in,
                              void* d_out, int out_size)
{
    const float* sr = (const float*)d_in[0];
    const float* hr = (const float*)d_in[1];
    float* out = (float*)d_out;

    edge_loss_kernel<<<NBLK, TPB>>>(sr, hr, out);
}

// round 12
// speedup vs baseline: 1.8128x; 1.0460x over previous
#include <cuda_runtime.h>
#include <cuda_fp16.h>

#define B_   32
#define C_   3
#define H_   512
#define W_   512
#define HW_  (H_ * W_)
#define ROWS 16
#define HB_  (H_ / ROWS)          // 32 row-bands per image
#define NBLK (B_ * HB_)           // 1024 blocks
#define TPB  256
#define TROWS (ROWS + 2)          // 18 tile rows (with halo)
#define STR  516                  // smem row stride in halves (1032 B)

// Tile layout (halves): image col c -> index c+2 (even -> 4B-aligned half2 ops)
// left halo (col -1) at index 1, right halo (col 512) at index 514.
// indices 0 and 515 zeroed.

__device__ float g_accum = 0.0f;
__device__ unsigned int g_count = 0;

__global__ __launch_bounds__(TPB, 8) void edge_loss_kernel(
    const float* __restrict__ sr, const float* __restrict__ hr,
    float* __restrict__ out)
{
    __shared__ __half g[TROWS * STR];   // 18,576 B -> 8 CTAs/SM (single wave)

    const int tid = threadIdx.x;
    const int b  = blockIdx.x / HB_;
    const int r0 = (blockIdx.x % HB_) * ROWS;
    const int rev = blockIdx.x & 1;     // odd bands load rows bottom->top (serpentine)

    const float* srb = sr + (size_t)b * C_ * HW_;
    const float* hrb = hr + (size_t)b * C_ * HW_;

    // Zero halo columns: indices 0,1 (left) and 514,515 (right) per tile row
    if (tid < 2 * TROWS) {
        int tr   = tid >> 1;
        int side = tid & 1;
        __half2* dst = (__half2*)&g[tr * STR + (side ? 514 : 0)];
        *dst = __floats2half2_rn(0.0f, 0.0f);
    }

    // Load halo'd gray-diff tile: 18 rows x 128 float4-chunks = 2304 tasks, 9/thread
    // FULL unroll: front-batched LDGs for MLP (proven).
    // Serpentine row order: adjacent bands touch shared halo rows at the same
    // time in their load phases -> second touch hits L2.
    #pragma unroll
    for (int it = 0; it < (TROWS * (W_ / 4)) / TPB; ++it) {
        int idx   = tid + it * TPB;
        int trl   = idx >> 7;          // / 128
        int tr    = rev ? (TROWS - 1 - trl) : trl;
        int chunk = idx & 127;
        int gr    = r0 + tr - 1;

        float4 d = make_float4(0.f, 0.f, 0.f, 0.f);
        if (gr >= 0 && gr < H_) {
            size_t off = (size_t)gr * W_ + chunk * 4;
            float4 s0 = *(const float4*)(srb + 0 * HW_ + off);
            float4 s1 = *(const float4*)(srb + 1 * HW_ + off);
            float4 s2 = *(const float4*)(srb + 2 * HW_ + off);
            float4 h0 = *(const float4*)(hrb + 0 * HW_ + off);
            float4 h1 = *(const float4*)(hrb + 1 * HW_ + off);
            float4 h2 = *(const float4*)(hrb + 2 * HW_ + off);
            d.x = 0.2989f * (s0.x - h0.x) + 0.587f * (s1.x - h1.x) + 0.114f * (s2.x - h2.x);
            d.y = 0.2989f * (s0.y - h0.y) + 0.587f * (s1.y - h1.y) + 0.114f * (s2.y - h2.y);
            d.z = 0.2989f * (s0.z - h0.z) + 0.587f * (s1.z - h1.z) + 0.114f * (s2.z - h2.z);
            d.w = 0.2989f * (s0.w - h0.w) + 0.587f * (s1.w - h1.w) + 0.114f * (s2.w - h2.w);
        }
        __half2* dst = (__half2*)&g[tr * STR + 2 + chunk * 4];   // 4B-aligned
        dst[0] = __floats2half2_rn(d.x, d.y);
        dst[1] = __floats2half2_rn(d.z, d.w);
    }
    __syncthreads();

    // Compute phase: 4 pixels per iter, half2 SIMD. 8 iters.
    const __half2 two = __floats2half2_rn(2.0f, 2.0f);
    float acc = 0.0f;
    #pragma unroll
    for (int it = 0; it < (ROWS * (W_ / 4)) / TPB; ++it) {   // 8 iters
        int idx = tid + it * TPB;
        int rr  = idx >> 7;            // 0..15
        int c4  = (idx & 127) * 4;     // 0,4,...,508
        const __half2* p0 = (const __half2*)&g[rr * STR + c4];
        const __half2* p1 = (const __half2*)&g[(rr + 1) * STR + c4];
        const __half2* p2 = (const __half2*)&g[(rr + 2) * STR + c4];

        __half2 P0 = p0[0], Q0 = p0[1], R0 = p0[2], S0 = p0[3];
        __half2 P1 = p1[0], Q1 = p1[1], R1 = p1[2], S1 = p1[3];
        __half2 P2 = p2[0], Q2 = p2[1], R2 = p2[2], S2 = p2[3];

        __half2 A0r0 = __halves2half2(__high2half(P0), __low2half(Q0));
        __half2 C0r0 = __halves2half2(__high2half(Q0), __low2half(R0));
        __half2 C1r0 = __halves2half2(__high2half(R0), __low2half(S0));
        __half2 A0r1 = __halves2half2(__high2half(P1), __low2half(Q1));
        __half2 C0r1 = __halves2half2(__high2half(Q1), __low2half(R1));
        __half2 C1r1 = __halves2half2(__high2half(R1), __low2half(S1));
        __half2 A0r2 = __halves2half2(__high2half(P2), __low2half(Q2));
        __half2 C0r2 = __halves2half2(__high2half(Q2), __low2half(R2));
        __half2 C1r2 = __halves2half2(__high2half(R2), __low2half(S2));

        __half2 gx0 = __hfma2(two, __hsub2(A0r1, C0r1),
                              __hadd2(__hsub2(A0r0, C0r0), __hsub2(A0r2, C0r2)));
        __half2 gy0 = __hsub2(__hfma2(two, Q0, __hadd2(A0r0, C0r0)),
                              __hfma2(two, Q2, __hadd2(A0r2, C0r2)));
        __half2 gx1 = __hfma2(two, __hsub2(C0r1, C1r1),
                              __hadd2(__hsub2(C0r0, C1r0), __hsub2(C0r2, C1r2)));
        __half2 gy1 = __hsub2(__hfma2(two, R0, __hadd2(C0r0, C1r0)),
                              __hfma2(two, R2, __hadd2(C0r2, C1r2)));

        __half2 s2h = __hadd2(__hadd2(__habs2(gx0), __habs2(gy0)),
                              __hadd2(__habs2(gx1), __habs2(gy1)));
        float2 sf = __half22float2(s2h);
        acc += sf.x + sf.y;
    }

    // Block reduce
    #pragma unroll
    for (int off = 16; off > 0; off >>= 1)
        acc += __shfl_xor_sync(0xFFFFFFFFu, acc, off);

    __shared__ float wsum[TPB / 32];
    if ((tid & 31) == 0) wsum[tid >> 5] = acc;
    __syncthreads();

    // tid0: one fire-and-forget atomic per block; NO trailing barrier.
    if (tid == 0) {
        float s = 0.0f;
        #pragma unroll
        for (int w = 0; w < TPB / 32; ++w) s += wsum[w];
        atomicAdd(&g_accum, s);
        __threadfence();
        unsigned int prev = atomicAdd(&g_count, 1u);
        if (prev == NBLK - 1) {
            float tot = atomicAdd(&g_accum, 0.0f);   // coherent L2 read
            out[0] = tot / (float)(B_ * (size_t)HW_);
            g_accum = 0.0f;   // reset for next replay
            g_count = 0;
        }
    }
}

extern "C" void kernel_launch(void* const* d_in, const int* in_sizes, int n_in,
                              void* d_out, int out_size)
{
    const float* sr = (const float*)d_in[0];
    const float* hr = (const float*)d_in[1];
    float* out = (float*)d_out;

    edge_loss_kernel<<<NBLK, TPB>>>(sr, hr, out);
}

// round 13
// speedup vs baseline: 1.8231x; 1.0057x over previous
#include <cuda_runtime.h>
#include <cuda_fp16.h>

#define B_   32
#define C_   3
#define H_   512
#define W_   512
#define HW_  (H_ * W_)
#define ROWS 16
#define HB_  (H_ / ROWS)          // 32 row-bands per image
#define NBLK (B_ * HB_)           // 1024 blocks
#define TPB  256
#define TROWS (ROWS + 2)          // 18 tile rows (with halo)
#define STR  516                  // smem row stride in halves (1032 B)

// Tile layout (halves): image col c -> index c+2 (even -> 4B-aligned half2 ops)
// left halo (col -1) at index 1, right halo (col 512) at index 514.
// indices 0 and 515 zeroed.

__device__ float g_accum = 0.0f;
__device__ unsigned int g_count = 0;

__device__ __forceinline__ void load_iter(
    __half* __restrict__ g,
    const float* __restrict__ srb, const float* __restrict__ hrb,
    int r0, int rev, int idx)
{
    int trl   = idx >> 7;                       // linear tile row 0..17
    int tr    = rev ? (TROWS - 1 - trl) : trl;  // serpentine
    int chunk = idx & 127;
    int gr    = r0 + tr - 1;

    float4 d = make_float4(0.f, 0.f, 0.f, 0.f);
    if (gr >= 0 && gr < H_) {
        size_t off = (size_t)gr * W_ + chunk * 4;
        float4 s0 = *(const float4*)(srb + 0 * HW_ + off);
        float4 s1 = *(const float4*)(srb + 1 * HW_ + off);
        float4 s2 = *(const float4*)(srb + 2 * HW_ + off);
        float4 h0 = *(const float4*)(hrb + 0 * HW_ + off);
        float4 h1 = *(const float4*)(hrb + 1 * HW_ + off);
        float4 h2 = *(const float4*)(hrb + 2 * HW_ + off);
        d.x = 0.2989f * (s0.x - h0.x) + 0.587f * (s1.x - h1.x) + 0.114f * (s2.x - h2.x);
        d.y = 0.2989f * (s0.y - h0.y) + 0.587f * (s1.y - h1.y) + 0.114f * (s2.y - h2.y);
        d.z = 0.2989f * (s0.z - h0.z) + 0.587f * (s1.z - h1.z) + 0.114f * (s2.z - h2.z);
        d.w = 0.2989f * (s0.w - h0.w) + 0.587f * (s1.w - h1.w) + 0.114f * (s2.w - h2.w);
    }
    __half2* dst = (__half2*)&g[tr * STR + 2 + chunk * 4];   // 4B-aligned
    dst[0] = __floats2half2_rn(d.x, d.y);
    dst[1] = __floats2half2_rn(d.z, d.w);
}

__device__ __forceinline__ float compute_iter(
    const __half* __restrict__ g, int rev, int idx)
{
    int rrl = idx >> 7;                     // linear pixel row 0..15
    int rr  = rev ? (ROWS - 1 - rrl) : rrl; // serpentine (match load order)
    int c4  = (idx & 127) * 4;              // 0,4,...,508
    const __half2* p0 = (const __half2*)&g[rr * STR + c4];
    const __half2* p1 = (const __half2*)&g[(rr + 1) * STR + c4];
    const __half2* p2 = (const __half2*)&g[(rr + 2) * STR + c4];

    const __half2 two = __floats2half2_rn(2.0f, 2.0f);

    __half2 P0 = p0[0], Q0 = p0[1], R0 = p0[2], S0 = p0[3];
    __half2 P1 = p1[0], Q1 = p1[1], R1 = p1[2], S1 = p1[3];
    __half2 P2 = p2[0], Q2 = p2[1], R2 = p2[2], S2 = p2[3];

    __half2 A0r0 = __halves2half2(__high2half(P0), __low2half(Q0));
    __half2 C0r0 = __halves2half2(__high2half(Q0), __low2half(R0));
    __half2 C1r0 = __halves2half2(__high2half(R0), __low2half(S0));
    __half2 A0r1 = __halves2half2(__high2half(P1), __low2half(Q1));
    __half2 C0r1 = __halves2half2(__high2half(Q1), __low2half(R1));
    __half2 C1r1 = __halves2half2(__high2half(R1), __low2half(S1));
    __half2 A0r2 = __halves2half2(__high2half(P2), __low2half(Q2));
    __half2 C0r2 = __halves2half2(__high2half(Q2), __low2half(R2));
    __half2 C1r2 = __halves2half2(__high2half(R2), __low2half(S2));

    __half2 gx0 = __hfma2(two, __hsub2(A0r1, C0r1),
                          __hadd2(__hsub2(A0r0, C0r0), __hsub2(A0r2, C0r2)));
    __half2 gy0 = __hsub2(__hfma2(two, Q0, __hadd2(A0r0, C0r0)),
                          __hfma2(two, Q2, __hadd2(A0r2, C0r2)));
    __half2 gx1 = __hfma2(two, __hsub2(C0r1, C1r1),
                          __hadd2(__hsub2(C0r0, C1r0), __hsub2(C0r2, C1r2)));
    __half2 gy1 = __hsub2(__hfma2(two, R0, __hadd2(C0r0, C1r0)),
                          __hfma2(two, R2, __hadd2(C0r2, C1r2)));

    __half2 s2h = __hadd2(__hadd2(__habs2(gx0), __habs2(gy0)),
                          __hadd2(__habs2(gx1), __habs2(gy1)));
    float2 sf = __half22float2(s2h);
    return sf.x + sf.y;
}

__global__ __launch_bounds__(TPB, 7) void edge_loss_kernel(
    const float* __restrict__ sr, const float* __restrict__ hr,
    float* __restrict__ out)
{
    __shared__ __half g[TROWS * STR];   // 18,576 B

    const int tid = threadIdx.x;
    const int b   = blockIdx.x / HB_;
    const int r0  = (blockIdx.x % HB_) * ROWS;
    const int rev = blockIdx.x & 1;     // serpentine band

    const float* srb = sr + (size_t)b * C_ * HW_;
    const float* hrb = hr + (size_t)b * C_ * HW_;

    // Zero halo columns: indices 0,1 (left) and 514,515 (right) per tile row
    if (tid < 2 * TROWS) {
        int tr   = tid >> 1;
        int side = tid & 1;
        __half2* dst = (__half2*)&g[tr * STR + (side ? 514 : 0)];
        *dst = __floats2half2_rn(0.0f, 0.0f);
    }

    // Stage 1: load linear tile rows 0..9 (5 iters)
    #pragma unroll
    for (int it = 0; it < 5; ++it)
        load_iter(g, srb, hrb, r0, rev, tid + it * TPB);
    __syncthreads();

    // Stage 2: interleave loading rows 10..17 with computing pixel rows 0..7.
    // Disjoint smem regions -> no hazard; LDGs overlap the LDS compute.
    float acc = 0.0f;
    #pragma unroll
    for (int it = 0; it < 4; ++it) {
        load_iter(g, srb, hrb, r0, rev, tid + (5 + it) * TPB);
        acc += compute_iter(g, rev, tid + it * TPB);
    }
    __syncthreads();

    // Stage 3: compute pixel rows 8..15 (4 iters)
    #pragma unroll
    for (int it = 0; it < 4; ++it)
        acc += compute_iter(g, rev, tid + (4 + it) * TPB);

    // Block reduce
    #pragma unroll
    for (int off = 16; off > 0; off >>= 1)
        acc += __shfl_xor_sync(0xFFFFFFFFu, acc, off);

    __shared__ float wsum[TPB / 32];
    if ((tid & 31) == 0) wsum[tid >> 5] = acc;
    __syncthreads();

    // tid0: one fire-and-forget atomic per block; NO trailing barrier.
    if (tid == 0) {
        float s = 0.0f;
        #pragma unroll
        for (int w = 0; w < TPB / 32; ++w) s += wsum[w];
        atomicAdd(&g_accum, s);
        __threadfence();
        unsigned int prev = atomicAdd(&g_count, 1u);
        if (prev == NBLK - 1) {
            float tot = atomicAdd(&g_accum, 0.0f);   // coherent L2 read
            out[0] = tot / (float)(B_ * (size_t)HW_);
            g_accum = 0.0f;   // reset for next replay
            g_count = 0;
        }
    }
}

extern "C" void kernel_launch(void* const* d_in, const int* in_sizes, int n_in,
                              void* d_out, int out_size)
{
    const float* sr = (const float*)d_in[0];
    const float* hr = (const float*)d_in[1];
    float* out = (float*)d_out;

    edge_loss_kernel<<<NBLK, TPB>>>(sr, hr, out);
}